// round 9
// baseline (speedup 1.0000x reference)
#include <cuda_runtime.h>

#define N_IN  1024
#define N_OUT 512
#define BATCH 128
#define M     (N_IN + 1)    // 1025 word lines (weights + bias row)
#define TJ    8             // j-columns per block
#define NCH   16            // i-chunks -> grid 64*16 = 1024 blocks = one wave
#define NJT   (N_OUT / TJ)  // 64 j-tiles
#define NI_MAX 65           // max rows per chunk

// ---- device scratch (no allocations allowed) ----
__device__ unsigned g_maxbits;              // bitwise max of |weights|; monotone, idempotent
__device__ float2   g_LS[M * BATCH];        // {lr, sign-bit-as-float} transposed [i][b]
__device__ float    g_Aacc[BATCH * N_OUT];  // atomic accum of s*(wp*pp - wn*qq)
__device__ float    g_Bacc[BATCH * N_OUT];  // atomic accum of s*(pp - qq)

__device__ __forceinline__ float ex2f_(float x) {
    float r; asm("ex2.approx.ftz.f32 %0, %1;" : "=f"(r) : "f"(x)); return r;
}
__device__ __forceinline__ float lg2f_(float x) {
    float r; asm("lg2.approx.ftz.f32 %0, %1;" : "=f"(r) : "f"(x)); return r;
}

// K0: (a) zero the atomic accumulators (fresh each graph replay);
// (b) LS transposed to [i][b] via 32x32 smem tiles:
//   l.x = 1 + log2|x|  (log2 of ratio = 2|x|; -inf at x==0 -> ex2 -> +0)
//   l.y = sign bit of x as float bits (0.0f / -0.0f)
__global__ void __launch_bounds__(256) k_prep_ls(const float* __restrict__ x) {
    __shared__ float2 sm[32][33];
    const int tid  = threadIdx.x;
    const int gtid = blockIdx.x * 256 + tid;

    // (a) zero A/B accumulators: 2*64K floats = 32K float4, grid has 33K threads
    {
        float4 z4 = make_float4(0.f, 0.f, 0.f, 0.f);
        if (gtid < (BATCH * N_OUT) / 4) {
            reinterpret_cast<float4*>(g_Aacc)[gtid] = z4;
            reinterpret_cast<float4*>(g_Bacc)[gtid] = z4;
        }
    }

    // (b) LS transpose
    if (blockIdx.x < 128) {
        const int it = blockIdx.x >> 2;          // 0..31  (i-tile)
        const int bt = blockIdx.x & 3;           // 0..3   (b-tile)
        const int i0 = it * 32, b0 = bt * 32;
        const int tx = tid & 31, tz = tid >> 5;  // tz = 0..7

        #pragma unroll
        for (int r = 0; r < 4; ++r) {            // read coalesced over i
            int bl = tz + r * 8;
            float xv = x[(b0 + bl) * N_IN + i0 + tx];
            float lr = lg2f_(fabsf(xv)) + 1.0f;
            unsigned sb = __float_as_uint(xv) & 0x80000000u;
            sm[bl][tx] = make_float2(lr, __uint_as_float(sb));
        }
        __syncthreads();
        #pragma unroll
        for (int r = 0; r < 4; ++r) {            // write coalesced over b
            int il = tz + r * 8;
            g_LS[(i0 + il) * BATCH + b0 + tx] = sm[tx][il];
        }
    } else if (tid < BATCH) {                    // blockIdx.x == 128: bias line (x == 1)
        g_LS[N_IN * BATCH + tid] = make_float2(1.0f, 0.0f);
    }
}

// K1: main. Block = 128 threads (all b), TJ=8, NCH=16 (1024 blocks = one wave).
// Fill computes {wp, -wn, Ep, En} and the block-local |w| max (each (i,j) visited
// exactly once grid-wide -> atomicMax builds the exact global max).
// Loop accumulates off-independent sums, sign folded in via XOR (ALU pipe):
//   A += wp*spp - wn*sqq ;  B += spp - sqq
// Epilogue: RED.F32 into compact accumulators (16 adds per output total, grid-wide).
__global__ void __launch_bounds__(128) k_main(const float* __restrict__ wp,
                                              const float* __restrict__ wn,
                                              const float* __restrict__ bp,
                                              const float* __restrict__ bn,
                                              const float* __restrict__ noise) {
    __shared__ float4 sP[NI_MAX * TJ];           // 65*8*16B = 8.3 KB

    const int jt = blockIdx.x;                   // 0..63
    const int ch = blockIdx.y;                   // 0..15
    const int j0 = jt * TJ;
    const int i0 = (ch * M) / NCH;
    const int i1 = ((ch + 1) * M) / NCH;
    const int ni = i1 - i0;
    const int b  = threadIdx.x;

    float mx = 0.0f;
    for (int t = b; t < ni * TJ; t += 128) {
        int ii = t >> 3, jj = t & (TJ - 1);
        int i = i0 + ii, j = j0 + jj;
        float wpv = (i < N_IN) ? wp[i * N_OUT + j] : bp[j];
        float wnv = (i < N_IN) ? wn[i * N_OUT + j] : bn[j];
        mx = fmaxf(mx, fmaxf(fabsf(wpv), fabsf(wnv)));
        float2 z = reinterpret_cast<const float2*>(noise)[i * N_OUT + j]; // cols (2j,2j+1), row i
        float4 P;
        P.x =  wpv;
        P.y = -wnv;
        P.z = lg2f_(2.8f + 0.2f * z.x);
        P.w = lg2f_(2.8f + 0.2f * z.y);
        sP[t] = P;
    }
    #pragma unroll
    for (int o = 16; o; o >>= 1)
        mx = fmaxf(mx, __shfl_xor_sync(0xFFFFFFFFu, mx, o));
    if ((b & 31) == 0)
        atomicMax(&g_maxbits, __float_as_uint(mx));   // exact on non-negative floats
    __syncthreads();

    float accA[TJ], accB[TJ];
    #pragma unroll
    for (int jj = 0; jj < TJ; ++jj) { accA[jj] = 0.0f; accB[jj] = 0.0f; }

    const float2* __restrict__ ls = &g_LS[i0 * BATCH + b];
    float2 l = ls[0];
    #pragma unroll 2
    for (int ii = 0; ii < ni; ++ii) {
        int nxt = (ii + 1 < ni) ? (ii + 1) : ii;
        float2 lnext = ls[nxt * BATCH];           // branch-free prefetch
        unsigned sbit = __float_as_uint(l.y);
        #pragma unroll
        for (int jj = 0; jj < TJ; ++jj) {
            float4 p = sP[ii * TJ + jj];          // smem broadcast
            float pp = ex2f_(p.z * l.x);          // ratio^Ep  (>= 0)
            float qq = ex2f_(p.w * l.x);          // ratio^En
            float spp = __uint_as_float(__float_as_uint(pp) ^ sbit);  // s*pp (LOP3)
            float sqq = __uint_as_float(__float_as_uint(qq) ^ sbit);  // s*qq
            accA[jj] = fmaf(p.x, spp, accA[jj]);
            accA[jj] = fmaf(p.y, sqq, accA[jj]);  // p.y = -wn
            accB[jj] += spp - sqq;
        }
        l = lnext;
    }

    #pragma unroll
    for (int jj = 0; jj < TJ; ++jj) {
        atomicAdd(&g_Aacc[b * N_OUT + j0 + jj], accA[jj]);   // RED.F32, spread addrs
        atomicAdd(&g_Bacc[b * N_OUT + j0 + jj], accB[jj]);
    }
}

// K2: finalize — out = 0.5*(A + 0.25*maxw * B). Reads only 512 KB, float2-vectorized.
__global__ void __launch_bounds__(256) k_finalize(float* __restrict__ out) {
    int t = blockIdx.x * blockDim.x + threadIdx.x;   // one float2 (two outputs) per thread
    if (t >= (BATCH * N_OUT) / 2) return;
    const float off = 0.25f * __uint_as_float(g_maxbits);
    float2 a = reinterpret_cast<const float2*>(g_Aacc)[t];
    float2 bb = reinterpret_cast<const float2*>(g_Bacc)[t];
    float2 r;
    r.x = 0.5f * fmaf(off, bb.x, a.x);
    r.y = 0.5f * fmaf(off, bb.y, a.y);
    reinterpret_cast<float2*>(out)[t] = r;
}

extern "C" void kernel_launch(void* const* d_in, const int* in_sizes, int n_in,
                              void* d_out, int out_size) {
    const float* x     = (const float*)d_in[0];   // (128, 1024)
    const float* w_pos = (const float*)d_in[1];   // (1024, 512)
    const float* w_neg = (const float*)d_in[2];   // (1024, 512)
    const float* b_pos = (const float*)d_in[3];   // (512,)
    const float* b_neg = (const float*)d_in[4];   // (512,)
    const float* noise = (const float*)d_in[5];   // (1025, 1024)
    float* out = (float*)d_out;                   // (128, 512)

    k_prep_ls<<<129, 256>>>(x);
    dim3 grid(NJT, NCH);
    k_main<<<grid, 128>>>(w_pos, w_neg, b_pos, b_neg, noise);
    k_finalize<<<(BATCH * N_OUT / 2 + 255) / 256, 256>>>(out);
}

// round 10
// speedup vs baseline: 1.1893x; 1.1893x over previous
#include <cuda_runtime.h>

#define N_IN  1024
#define N_OUT 512
#define BATCH 128
#define M     (N_IN + 1)    // 1025 word lines (weights + bias row)
#define TJ    8             // j-columns per block
#define NCH   16            // i-chunks -> grid 64*16 = 1024 blocks = one wave
#define NJT   (N_OUT / TJ)  // 64 j-tiles
#define NI_MAX 65           // max rows per chunk

// ---- device scratch (no allocations allowed) ----
__device__ unsigned g_maxbits;        // bitwise max of |weights|; monotone, idempotent across replays
__device__ float2   g_LS[M * BATCH];  // {lr, sign} transposed [i][b]

__device__ __forceinline__ float ex2f_(float x) {
    float r; asm("ex2.approx.ftz.f32 %0, %1;" : "=f"(r) : "f"(x)); return r;
}
__device__ __forceinline__ float lg2f_(float x) {
    float r; asm("lg2.approx.ftz.f32 %0, %1;" : "=f"(r) : "f"(x)); return r;
}

// K0: three independent jobs in one launch.
// (a) max|w| with high MLP: 65536 threads x 8 float4 = 512K float4 (wp then wn),
//     bias 0.5 seeded; atomicMax on non-negative float bits is exact.
// (b) zero d_out (poisoned; k_main REDs into it).
// (c) LS = {1+log2|x|, sign(x)} transposed to [i][b] via 32x32 smem tiles.
__global__ void __launch_bounds__(256) k_prep(const float* __restrict__ wp,
                                              const float* __restrict__ wn,
                                              const float* __restrict__ x,
                                              float* __restrict__ out) {
    __shared__ float2 sm[32][33];
    const int tid  = threadIdx.x;
    const int gtid = blockIdx.x * 256 + tid;          // 0 .. 65535 (grid = 256 blocks)

    // (a) max scan: wp and wn each 128K float4; thread handles 2 per array per step, 4 steps
    {
        const float4* wp4 = reinterpret_cast<const float4*>(wp);
        const float4* wn4 = reinterpret_cast<const float4*>(wn);
        float mx = 0.5f;
        #pragma unroll
        for (int s = 0; s < 2; ++s) {                 // 2 strides x 65536 threads = 128K float4
            int idx = s * 65536 + gtid;
            float4 a = wp4[idx], c = wn4[idx];
            mx = fmaxf(mx, fmaxf(fmaxf(fabsf(a.x), fabsf(a.y)), fmaxf(fabsf(a.z), fabsf(a.w))));
            mx = fmaxf(mx, fmaxf(fmaxf(fabsf(c.x), fabsf(c.y)), fmaxf(fabsf(c.z), fabsf(c.w))));
        }
        #pragma unroll
        for (int o = 16; o; o >>= 1)
            mx = fmaxf(mx, __shfl_xor_sync(0xFFFFFFFFu, mx, o));
        if ((tid & 31) == 0)
            atomicMax(&g_maxbits, __float_as_uint(mx));
    }

    // (b) zero output: 16K float4
    if (gtid < (BATCH * N_OUT) / 4)
        reinterpret_cast<float4*>(out)[gtid] = make_float4(0.f, 0.f, 0.f, 0.f);

    // (c) LS transpose: blocks 0..127 each handle a 32i x 32b tile of x
    if (blockIdx.x < 128) {
        const int it = blockIdx.x >> 2;          // 0..31  (i-tile)
        const int bt = blockIdx.x & 3;           // 0..3   (b-tile)
        const int i0 = it * 32, b0 = bt * 32;
        const int tx = tid & 31, tz = tid >> 5;  // tz = 0..7

        #pragma unroll
        for (int r = 0; r < 4; ++r) {            // read coalesced over i
            int bl = tz + r * 8;
            float xv = x[(b0 + bl) * N_IN + i0 + tx];
            float lr = lg2f_(fabsf(xv)) + 1.0f;  // log2(2|x|); -inf at 0 -> ex2 -> 0, s==0 kills term
            float s  = (xv > 0.0f) ? 1.0f : ((xv < 0.0f) ? -1.0f : 0.0f);
            sm[bl][tx] = make_float2(lr, s);
        }
        __syncthreads();
        #pragma unroll
        for (int r = 0; r < 4; ++r) {            // write coalesced over b
            int il = tz + r * 8;
            g_LS[(i0 + il) * BATCH + b0 + tx] = sm[tx][il];
        }
    } else if (blockIdx.x == 128 && tid < BATCH) {
        // bias word line: x == 1 -> lr = log2(2) = 1, s = 1
        g_LS[N_IN * BATCH + tid] = make_float2(1.0f, 1.0f);
    }
}

// K1: main (R3-proven inner loop). Block = 128 threads (all b), TJ=8, NCH=16 (1024 blocks).
// Params folded at fill (each (i,j) visited by exactly one block):
//   Cp = 0.5*(wp + off), Cn = -0.5*(wn + off), E = log2(2.8 + 0.2*z), off = 0.25*maxw
// Epilogue: 8 RED.F32 per thread into out (zeroed by k_prep) — 16 adds per output grid-wide.
__global__ void __launch_bounds__(128) k_main(const float* __restrict__ wp,
                                              const float* __restrict__ wn,
                                              const float* __restrict__ bp,
                                              const float* __restrict__ bn,
                                              const float* __restrict__ noise,
                                              float* __restrict__ out) {
    __shared__ float4 sP[NI_MAX * TJ];           // 65*8*16B = 8.3 KB

    const int jt = blockIdx.x;                   // 0..63
    const int ch = blockIdx.y;                   // 0..15
    const int j0 = jt * TJ;
    const int i0 = (ch * M) / NCH;
    const int i1 = ((ch + 1) * M) / NCH;
    const int ni = i1 - i0;
    const int b  = threadIdx.x;

    const float off = 0.25f * __uint_as_float(g_maxbits);

    for (int t = b; t < ni * TJ; t += 128) {
        int ii = t >> 3, jj = t & (TJ - 1);
        int i = i0 + ii, j = j0 + jj;
        float wpv = (i < N_IN) ? wp[i * N_OUT + j] : bp[j];
        float wnv = (i < N_IN) ? wn[i * N_OUT + j] : bn[j];
        float2 z = reinterpret_cast<const float2*>(noise)[i * N_OUT + j]; // cols (2j,2j+1), row i
        float4 P;
        P.x =  0.5f * (wpv + off);
        P.y = -0.5f * (wnv + off);
        P.z = lg2f_(2.8f + 0.2f * z.x);
        P.w = lg2f_(2.8f + 0.2f * z.y);
        sP[t] = P;
    }
    __syncthreads();

    float acc[TJ];
    #pragma unroll
    for (int jj = 0; jj < TJ; ++jj) acc[jj] = 0.0f;

    const float2* __restrict__ ls = &g_LS[i0 * BATCH + b];
    float2 l = ls[0];
    #pragma unroll 2
    for (int ii = 0; ii < ni; ++ii) {
        float2 lnext = (ii + 1 < ni) ? ls[(ii + 1) * BATCH] : l;  // prefetch next (i,b)
        #pragma unroll
        for (int jj = 0; jj < TJ; ++jj) {
            float4 p = sP[ii * TJ + jj];          // smem broadcast
            float pp = ex2f_(p.z * l.x);          // ratio^Ep
            float qq = ex2f_(p.w * l.x);          // ratio^En
            acc[jj] = fmaf(l.y, fmaf(p.x, pp, p.y * qq), acc[jj]);
        }
        l = lnext;
    }

    #pragma unroll
    for (int jj = 0; jj < TJ; ++jj)
        atomicAdd(&out[b * N_OUT + j0 + jj], acc[jj]);   // RED.F32, spread addresses
}

extern "C" void kernel_launch(void* const* d_in, const int* in_sizes, int n_in,
                              void* d_out, int out_size) {
    const float* x     = (const float*)d_in[0];   // (128, 1024)
    const float* w_pos = (const float*)d_in[1];   // (1024, 512)
    const float* w_neg = (const float*)d_in[2];   // (1024, 512)
    const float* b_pos = (const float*)d_in[3];   // (512,)
    const float* b_neg = (const float*)d_in[4];   // (512,)
    const float* noise = (const float*)d_in[5];   // (1025, 1024)
    float* out = (float*)d_out;                   // (128, 512)

    k_prep<<<256, 256>>>(w_pos, w_neg, x, out);
    dim3 grid(NJT, NCH);
    k_main<<<grid, 128>>>(w_pos, w_neg, b_pos, b_neg, noise, out);
}

// round 11
// speedup vs baseline: 1.2545x; 1.0548x over previous
#include <cuda_runtime.h>

#define N_IN  1024
#define N_OUT 512
#define BATCH 128
#define M     (N_IN + 1)    // 1025 word lines (weights + bias row)
#define TJ    8             // j-columns per block
#define NCH   16            // i-chunks -> grid 64*16 = 1024 blocks = one wave
#define NJT   (N_OUT / TJ)  // 64 j-tiles
#define NI_MAX 65           // max rows per chunk

// ---- device scratch (no allocations allowed) ----
__device__ unsigned g_maxbits;        // bitwise max of |weights|; monotone, idempotent across replays
__device__ float2   g_LS[M * BATCH];  // {lr, sign} transposed [i][b]

__device__ __forceinline__ float ex2f_(float x) {
    float r; asm("ex2.approx.ftz.f32 %0, %1;" : "=f"(r) : "f"(x)); return r;
}
__device__ __forceinline__ float lg2f_(float x) {
    float r; asm("lg2.approx.ftz.f32 %0, %1;" : "=f"(r) : "f"(x)); return r;
}

// K0: three independent jobs in one launch (R10-proven).
// (a) max|w| with high MLP (bias 0.5 seeded; atomicMax on non-negative float bits is exact);
// (b) zero d_out (poisoned; k_main REDs into it);
// (c) LS = {1+log2|x|, sign(x)} transposed to [i][b] via 32x32 smem tiles.
__global__ void __launch_bounds__(256) k_prep(const float* __restrict__ wp,
                                              const float* __restrict__ wn,
                                              const float* __restrict__ x,
                                              float* __restrict__ out) {
    __shared__ float2 sm[32][33];
    const int tid  = threadIdx.x;
    const int gtid = blockIdx.x * 256 + tid;          // 0 .. 65535 (grid = 256 blocks)

    // (a) max scan: wp and wn each 128K float4; 2 strides x 65536 threads
    {
        const float4* wp4 = reinterpret_cast<const float4*>(wp);
        const float4* wn4 = reinterpret_cast<const float4*>(wn);
        float mx = 0.5f;
        #pragma unroll
        for (int s = 0; s < 2; ++s) {
            int idx = s * 65536 + gtid;
            float4 a = wp4[idx], c = wn4[idx];
            mx = fmaxf(mx, fmaxf(fmaxf(fabsf(a.x), fabsf(a.y)), fmaxf(fabsf(a.z), fabsf(a.w))));
            mx = fmaxf(mx, fmaxf(fmaxf(fabsf(c.x), fabsf(c.y)), fmaxf(fabsf(c.z), fabsf(c.w))));
        }
        #pragma unroll
        for (int o = 16; o; o >>= 1)
            mx = fmaxf(mx, __shfl_xor_sync(0xFFFFFFFFu, mx, o));
        if ((tid & 31) == 0)
            atomicMax(&g_maxbits, __float_as_uint(mx));
    }

    // (b) zero output: 16K float4
    if (gtid < (BATCH * N_OUT) / 4)
        reinterpret_cast<float4*>(out)[gtid] = make_float4(0.f, 0.f, 0.f, 0.f);

    // (c) LS transpose: blocks 0..127 each handle a 32i x 32b tile of x
    if (blockIdx.x < 128) {
        const int it = blockIdx.x >> 2;          // 0..31  (i-tile)
        const int bt = blockIdx.x & 3;           // 0..3   (b-tile)
        const int i0 = it * 32, b0 = bt * 32;
        const int tx = tid & 31, tz = tid >> 5;  // tz = 0..7

        #pragma unroll
        for (int r = 0; r < 4; ++r) {            // read coalesced over i
            int bl = tz + r * 8;
            float xv = x[(b0 + bl) * N_IN + i0 + tx];
            float lr = lg2f_(fabsf(xv)) + 1.0f;  // log2(2|x|); -inf at 0 -> ex2 -> 0, s==0 kills term
            float s  = (xv > 0.0f) ? 1.0f : ((xv < 0.0f) ? -1.0f : 0.0f);
            sm[bl][tx] = make_float2(lr, s);
        }
        __syncthreads();
        #pragma unroll
        for (int r = 0; r < 4; ++r) {            // write coalesced over b
            int il = tz + r * 8;
            g_LS[(i0 + il) * BATCH + b0 + tx] = sm[tx][il];
        }
    } else if (blockIdx.x == 128 && tid < BATCH) {
        g_LS[N_IN * BATCH + tid] = make_float2(1.0f, 1.0f);   // bias line: x == 1
    }
}

// One (i,b) pair against TJ=8 columns from the smem tile.
__device__ __forceinline__ void pair8_(const float4* __restrict__ sProw,
                                       float2 l, float* __restrict__ acc) {
    #pragma unroll
    for (int jj = 0; jj < TJ; ++jj) {
        float4 p = sProw[jj];                    // smem broadcast
        float pp = ex2f_(p.z * l.x);             // ratio^Ep
        float qq = ex2f_(p.w * l.x);             // ratio^En
        acc[jj] = fmaf(l.y, fmaf(p.x, pp, p.y * qq), acc[jj]);
    }
}

// K1: main. Block = 128 threads (all b), TJ=8, NCH=16 (1024 blocks = one wave).
// Params folded at fill: Cp = 0.5*(wp+off), Cn = -0.5*(wn+off), E = log2(2.8+0.2*z).
// ls streamed through a 4-deep register double-buffer (prefetch distance 4 i-iters
// > L2 latency), sb-loop unrolled x2 so buffer selection is compile-time.
// Chunk sizes: ni = 64 (ch 0..14) or 65 (ch 15) -> 16 sub-blocks of 4 + clamped tail.
__global__ void __launch_bounds__(128) k_main(const float* __restrict__ wp,
                                              const float* __restrict__ wn,
                                              const float* __restrict__ bp,
                                              const float* __restrict__ bn,
                                              const float* __restrict__ noise,
                                              float* __restrict__ out) {
    __shared__ float4 sP[NI_MAX * TJ];           // 65*8*16B = 8.3 KB

    const int jt = blockIdx.x;                   // 0..63
    const int ch = blockIdx.y;                   // 0..15
    const int j0 = jt * TJ;
    const int i0 = (ch * M) / NCH;
    const int i1 = ((ch + 1) * M) / NCH;
    const int ni = i1 - i0;                      // 64 or 65
    const int b  = threadIdx.x;

    const float off = 0.25f * __uint_as_float(g_maxbits);

    for (int t = b; t < ni * TJ; t += 128) {
        int ii = t >> 3, jj = t & (TJ - 1);
        int i = i0 + ii, j = j0 + jj;
        float wpv = (i < N_IN) ? wp[i * N_OUT + j] : bp[j];
        float wnv = (i < N_IN) ? wn[i * N_OUT + j] : bn[j];
        float2 z = reinterpret_cast<const float2*>(noise)[i * N_OUT + j]; // cols (2j,2j+1), row i
        float4 P;
        P.x =  0.5f * (wpv + off);
        P.y = -0.5f * (wnv + off);
        P.z = lg2f_(2.8f + 0.2f * z.x);
        P.w = lg2f_(2.8f + 0.2f * z.y);
        sP[t] = P;
    }
    __syncthreads();

    float acc[TJ];
    #pragma unroll
    for (int jj = 0; jj < TJ; ++jj) acc[jj] = 0.0f;

    const float2* __restrict__ lsp = &g_LS[i0 * BATCH + b];
    const int last = ni - 1;

    float2 A[4], B[4];
    #pragma unroll
    for (int k = 0; k < 4; ++k) A[k] = lsp[k * BATCH];

    // 16 sub-blocks of 4 (covers i-local 0..63); unroll-by-2 over sub-blocks
    for (int sb = 0; sb < 16; sb += 2) {
        int base1 = (sb + 1) * 4;
        #pragma unroll
        for (int k = 0; k < 4; ++k) {
            int idx = base1 + k; idx = (idx < ni) ? idx : last;
            B[k] = lsp[idx * BATCH];
        }
        #pragma unroll
        for (int k = 0; k < 4; ++k)
            pair8_(&sP[(sb * 4 + k) * TJ], A[k], acc);

        int base2 = (sb + 2) * 4;
        #pragma unroll
        for (int k = 0; k < 4; ++k) {
            int idx = base2 + k; idx = (idx < ni) ? idx : last;
            A[k] = lsp[idx * BATCH];
        }
        #pragma unroll
        for (int k = 0; k < 4; ++k)
            pair8_(&sP[((sb + 1) * 4 + k) * TJ], B[k], acc);
    }
    // tail: i-local 64 when ni == 65 (A[0] holds the clamped last element)
    if (ni > 64)
        pair8_(&sP[64 * TJ], A[0], acc);

    #pragma unroll
    for (int jj = 0; jj < TJ; ++jj)
        atomicAdd(&out[b * N_OUT + j0 + jj], acc[jj]);   // RED.F32, spread addresses
}

extern "C" void kernel_launch(void* const* d_in, const int* in_sizes, int n_in,
                              void* d_out, int out_size) {
    const float* x     = (const float*)d_in[0];   // (128, 1024)
    const float* w_pos = (const float*)d_in[1];   // (1024, 512)
    const float* w_neg = (const float*)d_in[2];   // (1024, 512)
    const float* b_pos = (const float*)d_in[3];   // (512,)
    const float* b_neg = (const float*)d_in[4];   // (512,)
    const float* noise = (const float*)d_in[5];   // (1025, 1024)
    float* out = (float*)d_out;                   // (128, 512)

    k_prep<<<256, 256>>>(w_pos, w_neg, x, out);
    dim3 grid(NJT, NCH);
    k_main<<<grid, 128>>>(w_pos, w_neg, b_pos, b_neg, noise, out);
}